// round 3
// baseline (speedup 1.0000x reference)
#include <cuda_runtime.h>
#include <math_constants.h>

#define MAXN 100000
#define MAXE 700000
#define NH   8
#define NC   16
#define HC   128

// Scratch (allocation-free rule: __device__ globals)
__device__ float g_xw[MAXN * HC];     // x @ W            [N, H*C]
__device__ float g_atgt[MAXN * NH];   // dot(xw, att[:, :C])  (target/dst term)
__device__ float g_asrc[MAXN * NH];   // dot(xw, att[:, C:])  (source/src term)
__device__ float g_amax[MAXN * NH];   // segment max
__device__ float g_denom[MAXN * NH];  // segment sum of exp
__device__ int   g_is64;              // 1 if edge_index buffer is int64

__device__ __forceinline__ void atomicMaxFloat(float* addr, float value) {
    if (value >= 0.f) atomicMax((int*)addr, __float_as_int(value));
    else              atomicMin((unsigned int*)addr, __float_as_uint(value));
}

// ---------------------------------------------------------------------------
// K0: detect edge dtype. If int64, the high word of every (nonneg, < 2^31)
// index is 0; if int32, odd-position words are random indices (nonzero w.h.p.)
// ---------------------------------------------------------------------------
__global__ void k_detect(const int* __restrict__ ei32, int E) {
    if (threadIdx.x == 0 && blockIdx.x == 0) {
        int m = E < 128 ? E : 128;
        int nz = 0;
        for (int i = 0; i < m; i++) nz |= ei32[2 * i + 1];
        g_is64 = (nz == 0) ? 1 : 0;
    }
}

// ---------------------------------------------------------------------------
// K1: xw = x @ W   ([n,128] @ [128,128]), register-blocked FFMA GEMM.
// Block = 256 threads, tile = 64 rows x 128 cols, per-thread 4x8.
// Dynamic smem: W full (64KB) + X tile (32KB) = 96KB.
// ---------------------------------------------------------------------------
__global__ void k_gemm(const float* __restrict__ x, const float* __restrict__ w, int n) {
    extern __shared__ float smem[];
    float* sW = smem;              // 128*128
    float* sX = smem + 128 * 128;  // 64*128
    int tid = threadIdx.x;

    const float4* w4 = (const float4*)w;
    float4* sW4 = (float4*)sW;
#pragma unroll
    for (int i = 0; i < 16; i++) sW4[tid + i * 256] = w4[tid + i * 256];

    int row0 = blockIdx.x * 64;
    int tile_rows = n - row0; if (tile_rows > 64) tile_rows = 64;
    float4* sX4 = (float4*)sX;
    const float4* x4 = (const float4*)(x + (long)row0 * 128);
#pragma unroll
    for (int i = 0; i < 8; i++) {
        int idx = tid + i * 256;   // float4 index within 64x32
        int r = idx >> 5;
        sX4[idx] = (r < tile_rows) ? x4[idx] : make_float4(0.f, 0.f, 0.f, 0.f);
    }
    __syncthreads();

    int ty = tid >> 4, tx = tid & 15;
    const float* pX0 = sX + (ty * 4 + 0) * 128;
    const float* pX1 = sX + (ty * 4 + 1) * 128;
    const float* pX2 = sX + (ty * 4 + 2) * 128;
    const float* pX3 = sX + (ty * 4 + 3) * 128;

    float acc[4][8];
#pragma unroll
    for (int r = 0; r < 4; r++)
#pragma unroll
        for (int j = 0; j < 8; j++) acc[r][j] = 0.f;

#pragma unroll 8
    for (int k = 0; k < 128; k++) {
        float xv0 = pX0[k], xv1 = pX1[k], xv2 = pX2[k], xv3 = pX3[k];
        float4 wa = *(const float4*)(sW + k * 128 + tx * 8);
        float4 wb = *(const float4*)(sW + k * 128 + tx * 8 + 4);
        float wv[8] = {wa.x, wa.y, wa.z, wa.w, wb.x, wb.y, wb.z, wb.w};
#pragma unroll
        for (int j = 0; j < 8; j++) {
            acc[0][j] += xv0 * wv[j];
            acc[1][j] += xv1 * wv[j];
            acc[2][j] += xv2 * wv[j];
            acc[3][j] += xv3 * wv[j];
        }
    }

#pragma unroll
    for (int r = 0; r < 4; r++) {
        int row = row0 + ty * 4 + r;
        if (row < n) {
            float4* o = (float4*)(g_xw + (long)row * 128 + tx * 8);
            o[0] = make_float4(acc[r][0], acc[r][1], acc[r][2], acc[r][3]);
            o[1] = make_float4(acc[r][4], acc[r][5], acc[r][6], acc[r][7]);
        }
    }
}

// ---------------------------------------------------------------------------
// K2: init — zero out (float4), amax=-inf, denom=0.
// ---------------------------------------------------------------------------
__global__ void k_init(float* __restrict__ out, int n) {
    int i = blockIdx.x * blockDim.x + threadIdx.x;
    int total4 = n * 32;
    if (i < total4) ((float4*)out)[i] = make_float4(0.f, 0.f, 0.f, 0.f);
    if (i < n * NH) { g_amax[i] = -CUDART_INF_F; g_denom[i] = 0.f; }
}

// ---------------------------------------------------------------------------
// K3: per-node attention dot products. One thread per (node, head).
// att layout: [1, H, 2C] -> att[h*32 + c]; first 16 for x_i (dst), next 16 x_j.
// ---------------------------------------------------------------------------
__global__ void k_dots(const float* __restrict__ att, int n) {
    int i = blockIdx.x * blockDim.x + threadIdx.x;
    if (i >= n * NH) return;
    int h = i & 7, node = i >> 3;
    const float4* v  = (const float4*)(g_xw + (long)node * 128 + h * 16);
    const float4* at = (const float4*)(att + h * 32);
    const float4* as = (const float4*)(att + h * 32 + 16);
    float s1 = 0.f, s2 = 0.f;
#pragma unroll
    for (int j = 0; j < 4; j++) {
        float4 a = v[j], b = at[j], c = as[j];
        s1 += a.x * b.x + a.y * b.y + a.z * b.z + a.w * b.w;
        s2 += a.x * c.x + a.y * c.y + a.z * c.z + a.w * c.w;
    }
    g_atgt[i] = s1;
    g_asrc[i] = s2;
}

// Edge index fetch, dtype-agnostic: s = g_is64 shift (0 for int32, 1 for int64;
// int64 low word at position 2*idx since values < 2^31 and little-endian).
__device__ __forceinline__ int edge_at(const int* ei32, int idx, int shift) {
    return ei32[idx << shift];
}

// ---------------------------------------------------------------------------
// K4: segment max of leaky-relu logits. One thread per (edge, head).
// ---------------------------------------------------------------------------
__global__ void k_max(const int* __restrict__ ei32, int E) {
    int i = blockIdx.x * blockDim.x + threadIdx.x;
    if (i >= E * NH) return;
    int sh = g_is64;
    int e = i >> 3, h = i & 7;
    int s = edge_at(ei32, e, sh);
    int d = edge_at(ei32, E + e, sh);
    float a = g_atgt[d * NH + h] + g_asrc[s * NH + h];
    a = a > 0.f ? a : 0.2f * a;
    atomicMaxFloat(&g_amax[d * NH + h], a);
}

// ---------------------------------------------------------------------------
// K5: exp + denom + weighted scatter of source features into out.
// One thread per (edge, head) handles 16 channels.
// ---------------------------------------------------------------------------
__global__ void k_scatter(const int* __restrict__ ei32, float* __restrict__ out, int E) {
    int i = blockIdx.x * blockDim.x + threadIdx.x;
    if (i >= E * NH) return;
    int sh = g_is64;
    int e = i >> 3, h = i & 7;
    int s = edge_at(ei32, e, sh);
    int d = edge_at(ei32, E + e, sh);
    int dh = d * NH + h;
    float a = g_atgt[dh] + g_asrc[s * NH + h];
    a = a > 0.f ? a : 0.2f * a;
    float ex = __expf(a - g_amax[dh]);
    atomicAdd(&g_denom[dh], ex);
    const float4* xs = (const float4*)(g_xw + (long)s * 128 + h * 16);
    float* op = out + (long)d * 128 + h * 16;
#pragma unroll
    for (int j = 0; j < 4; j++) {
        float4 v = xs[j];
        atomicAdd(op + j * 4 + 0, ex * v.x);
        atomicAdd(op + j * 4 + 1, ex * v.y);
        atomicAdd(op + j * 4 + 2, ex * v.z);
        atomicAdd(op + j * 4 + 3, ex * v.w);
    }
}

// ---------------------------------------------------------------------------
// K6: normalize by denom, add bias. One thread per float4 of out.
// ---------------------------------------------------------------------------
__global__ void k_final(float* __restrict__ out, const float* __restrict__ bias, int n) {
    int i = blockIdx.x * blockDim.x + threadIdx.x;
    if (i >= n * 32) return;
    int node = i >> 5;
    int q = i & 31;
    int h = q >> 2;
    float inv = 1.f / g_denom[node * NH + h];
    float4 v = ((float4*)out)[i];
    float4 b = ((const float4*)bias)[q];
    v.x = v.x * inv + b.x;
    v.y = v.y * inv + b.y;
    v.z = v.z * inv + b.z;
    v.w = v.w * inv + b.w;
    ((float4*)out)[i] = v;
}

// ---------------------------------------------------------------------------
// Input slots identified by element count (all six are strictly distinct):
// x (n*128 ~12.8M) > edge_index (2E ~1.4M) > mask (n ~100k) > weight (16384)
// > att (256) > bias (128).
// ---------------------------------------------------------------------------
extern "C" void kernel_launch(void* const* d_in, const int* in_sizes, int n_in,
                              void* d_out, int out_size) {
    int order[16];
    for (int i = 0; i < n_in; i++) order[i] = i;
    for (int a = 0; a < n_in; a++)
        for (int b = a + 1; b < n_in; b++)
            if (in_sizes[order[b]] > in_sizes[order[a]]) {
                int t = order[a]; order[a] = order[b]; order[b] = t;
            }
    const float* x    = (const float*)d_in[order[0]];
    const int*   ei32 = (const int*)  d_in[order[1]];   // int32 or int64, detected on device
    const float* w    = (const float*)d_in[order[3]];
    const float* att  = (const float*)d_in[order[4]];
    const float* bias = (const float*)d_in[order[5]];
    float*       out  = (float*)d_out;

    int n = in_sizes[order[0]] / 128;  // num nodes
    int E = in_sizes[order[1]] / 2;    // num edges (incl. self-loops)

    k_detect<<<1, 32>>>(ei32, E);

    cudaFuncSetAttribute(k_gemm, cudaFuncAttributeMaxDynamicSharedMemorySize, 98304);
    k_gemm<<<(n + 63) / 64, 256, 98304>>>(x, w, n);

    int t4 = n * 32;
    k_init<<<(t4 + 255) / 256, 256>>>(out, n);

    int tnh = n * NH;
    k_dots<<<(tnh + 255) / 256, 256>>>(att, n);

    int teh = E * NH;
    k_max<<<(teh + 255) / 256, 256>>>(ei32, E);
    k_scatter<<<(teh + 255) / 256, 256>>>(ei32, out, E);

    k_final<<<(t4 + 255) / 256, 256>>>(out, bias, n);
}

// round 4
// speedup vs baseline: 2.0198x; 2.0198x over previous
#include <cuda_runtime.h>
#include <math_constants.h>

#define MAXN 100000
#define NH   8
#define HC   128

// Scratch (allocation-free rule: __device__ globals)
__device__ float g_xw[MAXN * HC];     // x @ W            [N, H*C]
__device__ float g_atgt[MAXN * NH];   // dot(xw, att[:, :C])  (target/dst term)
__device__ float g_asrc[MAXN * NH];   // dot(xw, att[:, C:])  (source/src term)
__device__ float g_denom[MAXN * NH];  // segment sum of exp
__device__ int   g_is64;              // 1 if edge_index buffer is int64

// ---------------------------------------------------------------------------
// K0: detect edge dtype. If int64, high word of every index (< 2^31) is 0;
// if int32, odd-position words are random indices (nonzero w.h.p.)
// ---------------------------------------------------------------------------
__global__ void k_detect(const int* __restrict__ ei32, int E) {
    if (threadIdx.x == 0 && blockIdx.x == 0) {
        int m = E < 128 ? E : 128;
        int nz = 0;
        for (int i = 0; i < m; i++) nz |= ei32[2 * i + 1];
        g_is64 = (nz == 0) ? 1 : 0;
    }
}

// ---------------------------------------------------------------------------
// K1: xw = x @ W   ([n,128] @ [128,128]), register-blocked FFMA GEMM.
// ---------------------------------------------------------------------------
__global__ void k_gemm(const float* __restrict__ x, const float* __restrict__ w, int n) {
    extern __shared__ float smem[];
    float* sW = smem;              // 128*128
    float* sX = smem + 128 * 128;  // 64*128
    int tid = threadIdx.x;

    const float4* w4 = (const float4*)w;
    float4* sW4 = (float4*)sW;
#pragma unroll
    for (int i = 0; i < 16; i++) sW4[tid + i * 256] = w4[tid + i * 256];

    int row0 = blockIdx.x * 64;
    int tile_rows = n - row0; if (tile_rows > 64) tile_rows = 64;
    float4* sX4 = (float4*)sX;
    const float4* x4 = (const float4*)(x + (long)row0 * 128);
#pragma unroll
    for (int i = 0; i < 8; i++) {
        int idx = tid + i * 256;
        int r = idx >> 5;
        sX4[idx] = (r < tile_rows) ? x4[idx] : make_float4(0.f, 0.f, 0.f, 0.f);
    }
    __syncthreads();

    int ty = tid >> 4, tx = tid & 15;
    const float* pX0 = sX + (ty * 4 + 0) * 128;
    const float* pX1 = sX + (ty * 4 + 1) * 128;
    const float* pX2 = sX + (ty * 4 + 2) * 128;
    const float* pX3 = sX + (ty * 4 + 3) * 128;

    float acc[4][8];
#pragma unroll
    for (int r = 0; r < 4; r++)
#pragma unroll
        for (int j = 0; j < 8; j++) acc[r][j] = 0.f;

#pragma unroll 8
    for (int k = 0; k < 128; k++) {
        float xv0 = pX0[k], xv1 = pX1[k], xv2 = pX2[k], xv3 = pX3[k];
        float4 wa = *(const float4*)(sW + k * 128 + tx * 8);
        float4 wb = *(const float4*)(sW + k * 128 + tx * 8 + 4);
        float wv[8] = {wa.x, wa.y, wa.z, wa.w, wb.x, wb.y, wb.z, wb.w};
#pragma unroll
        for (int j = 0; j < 8; j++) {
            acc[0][j] += xv0 * wv[j];
            acc[1][j] += xv1 * wv[j];
            acc[2][j] += xv2 * wv[j];
            acc[3][j] += xv3 * wv[j];
        }
    }

#pragma unroll
    for (int r = 0; r < 4; r++) {
        int row = row0 + ty * 4 + r;
        if (row < n) {
            float4* o = (float4*)(g_xw + (long)row * 128 + tx * 8);
            o[0] = make_float4(acc[r][0], acc[r][1], acc[r][2], acc[r][3]);
            o[1] = make_float4(acc[r][4], acc[r][5], acc[r][6], acc[r][7]);
        }
    }
}

// ---------------------------------------------------------------------------
// K2: init — zero out (float4), denom=0.
// ---------------------------------------------------------------------------
__global__ void k_init(float* __restrict__ out, int n) {
    int i = blockIdx.x * blockDim.x + threadIdx.x;
    int total4 = n * 32;
    if (i < total4) ((float4*)out)[i] = make_float4(0.f, 0.f, 0.f, 0.f);
    if (i < n * NH) g_denom[i] = 0.f;
}

// ---------------------------------------------------------------------------
// K3: per-node attention dot products. One thread per (node, head).
// ---------------------------------------------------------------------------
__global__ void k_dots(const float* __restrict__ att, int n) {
    int i = blockIdx.x * blockDim.x + threadIdx.x;
    if (i >= n * NH) return;
    int h = i & 7, node = i >> 3;
    const float4* v  = (const float4*)(g_xw + (long)node * 128 + h * 16);
    const float4* at = (const float4*)(att + h * 32);
    const float4* as = (const float4*)(att + h * 32 + 16);
    float s1 = 0.f, s2 = 0.f;
#pragma unroll
    for (int j = 0; j < 4; j++) {
        float4 a = v[j], b = at[j], c = as[j];
        s1 += a.x * b.x + a.y * b.y + a.z * b.z + a.w * b.w;
        s2 += a.x * c.x + a.y * c.y + a.z * c.z + a.w * c.w;
    }
    g_atgt[i] = s1;
    g_asrc[i] = s2;
}

__device__ __forceinline__ int edge_at(const int* ei32, int idx, int shift) {
    return ei32[idx << shift];
}

__device__ __forceinline__ void red_add_v4(float* p, float a, float b, float c, float d) {
    asm volatile("red.global.add.v4.f32 [%0], {%1, %2, %3, %4};"
                 :: "l"(p), "f"(a), "f"(b), "f"(c), "f"(d) : "memory");
}

// ---------------------------------------------------------------------------
// K5: exp + denom + weighted scatter of source features into out.
// One thread per (edge, head) handles 16 channels. No max subtraction:
// logits are O(10) so exp cannot overflow; softmax is shift-invariant.
// ---------------------------------------------------------------------------
__global__ void k_scatter(const int* __restrict__ ei32, float* __restrict__ out, int E) {
    int i = blockIdx.x * blockDim.x + threadIdx.x;
    if (i >= E * NH) return;
    int sh = g_is64;
    int e = i >> 3, h = i & 7;
    int s = edge_at(ei32, e, sh);
    int d = edge_at(ei32, E + e, sh);
    int dh = d * NH + h;
    float a = g_atgt[dh] + g_asrc[s * NH + h];
    a = a > 0.f ? a : 0.2f * a;
    float ex = __expf(a);
    atomicAdd(&g_denom[dh], ex);
    const float4* xs = (const float4*)(g_xw + (long)s * 128 + h * 16);
    float* op = out + (long)d * 128 + h * 16;
#pragma unroll
    for (int j = 0; j < 4; j++) {
        float4 v = xs[j];
        red_add_v4(op + j * 4, ex * v.x, ex * v.y, ex * v.z, ex * v.w);
    }
}

// ---------------------------------------------------------------------------
// K6: normalize by denom, add bias. One thread per float4 of out.
// ---------------------------------------------------------------------------
__global__ void k_final(float* __restrict__ out, const float* __restrict__ bias, int n) {
    int i = blockIdx.x * blockDim.x + threadIdx.x;
    if (i >= n * 32) return;
    int node = i >> 5;
    int q = i & 31;
    int h = q >> 2;
    float inv = 1.f / g_denom[node * NH + h];
    float4 v = ((float4*)out)[i];
    float4 b = ((const float4*)bias)[q];
    v.x = v.x * inv + b.x;
    v.y = v.y * inv + b.y;
    v.z = v.z * inv + b.z;
    v.w = v.w * inv + b.w;
    ((float4*)out)[i] = v;
}

// ---------------------------------------------------------------------------
extern "C" void kernel_launch(void* const* d_in, const int* in_sizes, int n_in,
                              void* d_out, int out_size) {
    int order[16];
    for (int i = 0; i < n_in; i++) order[i] = i;
    for (int a = 0; a < n_in; a++)
        for (int b = a + 1; b < n_in; b++)
            if (in_sizes[order[b]] > in_sizes[order[a]]) {
                int t = order[a]; order[a] = order[b]; order[b] = t;
            }
    const float* x    = (const float*)d_in[order[0]];
    const int*   ei32 = (const int*)  d_in[order[1]];
    const float* w    = (const float*)d_in[order[3]];
    const float* att  = (const float*)d_in[order[4]];
    const float* bias = (const float*)d_in[order[5]];
    float*       out  = (float*)d_out;

    int n = in_sizes[order[0]] / 128;  // num nodes
    int E = in_sizes[order[1]] / 2;    // num edges (incl. self-loops)

    k_detect<<<1, 32>>>(ei32, E);

    cudaFuncSetAttribute(k_gemm, cudaFuncAttributeMaxDynamicSharedMemorySize, 98304);
    k_gemm<<<(n + 63) / 64, 256, 98304>>>(x, w, n);

    int t4 = n * 32;
    k_init<<<(t4 + 255) / 256, 256>>>(out, n);

    int tnh = n * NH;
    k_dots<<<(tnh + 255) / 256, 256>>>(att, n);

    int teh = E * NH;
    k_scatter<<<(teh + 255) / 256, 256>>>(ei32, out, E);

    k_final<<<(t4 + 255) / 256, 256>>>(out, bias, n);
}

// round 5
// speedup vs baseline: 2.7350x; 1.3541x over previous
#include <cuda_runtime.h>
#include <math_constants.h>

#define MAXN 100000
#define NH   8
#define HC   128

__device__ float g_xw[MAXN * HC];     // x @ W            [N, H*C]
__device__ float g_atgt[MAXN * NH];   // dot(xw, att[:, :C])
__device__ float g_asrc[MAXN * NH];   // dot(xw, att[:, C:])
__device__ float g_denom[MAXN * NH];  // segment sum of exp
__device__ int   g_is64;

// ---------------------------------------------------------------------------
__global__ void k_detect(const int* __restrict__ ei32, int E) {
    if (threadIdx.x == 0 && blockIdx.x == 0) {
        int m = E < 128 ? E : 128;
        int nz = 0;
        for (int i = 0; i < m; i++) nz |= ei32[2 * i + 1];
        g_is64 = (nz == 0) ? 1 : 0;
    }
}

__device__ __forceinline__ unsigned cvt_tf32(float f) {
    unsigned r;
    asm("cvt.rna.tf32.f32 %0, %1;" : "=r"(r) : "f"(f));
    return r;
}

// ---------------------------------------------------------------------------
// K1: tf32 tensor-core GEMM  xw = x @ W  (per block: 128 rows x 128 cols),
// fused epilogue computes per-(node,head) attention dots a_tgt, a_src.
// Block = 256 threads (8 warps); warp w owns 16 rows. mma.m16n8k8 tf32.
// smem: sA[128][132] + sB[128][132] (W transposed to [n][k]) + att[256].
// ---------------------------------------------------------------------------
#define SA_STRIDE 132
__global__ void __launch_bounds__(256) k_gemm_tf32(
        const float* __restrict__ x, const float* __restrict__ w,
        const float* __restrict__ att, int n) {
    extern __shared__ float smem[];
    float* sA   = smem;                    // [128][132] tf32 bits
    float* sB   = smem + 128 * SA_STRIDE;  // [n=128][k=132] tf32 bits (W^T)
    float* sAtt = smem + 2 * 128 * SA_STRIDE;  // 256

    int tid  = threadIdx.x;
    int lane = tid & 31, warp = tid >> 5;
    int g = lane >> 2, t = lane & 3;       // quad row / col-in-quad
    int row0g = blockIdx.x * 128;

    sAtt[tid] = att[tid];

    // Fill sB = W^T (with tf32 rounding). W is [k=128][n=128] row-major.
#pragma unroll
    for (int i = 0; i < 16; i++) {
        int idx = tid + i * 256;           // over 4096 float4
        float4 v = ((const float4*)w)[idx];
        int k  = idx >> 5;
        int n4 = (idx & 31) * 4;
        sB[(n4 + 0) * SA_STRIDE + k] = __uint_as_float(cvt_tf32(v.x));
        sB[(n4 + 1) * SA_STRIDE + k] = __uint_as_float(cvt_tf32(v.y));
        sB[(n4 + 2) * SA_STRIDE + k] = __uint_as_float(cvt_tf32(v.z));
        sB[(n4 + 3) * SA_STRIDE + k] = __uint_as_float(cvt_tf32(v.w));
    }

    // Fill sA = x tile (zero-padded past n), tf32-rounded.
    const float4* x4 = (const float4*)(x + (size_t)row0g * 128);
#pragma unroll
    for (int i = 0; i < 16; i++) {
        int idx = tid + i * 256;           // 128 rows x 32 float4
        int r  = idx >> 5;
        int c4 = (idx & 31) * 4;
        float4 v = (row0g + r < n) ? x4[idx] : make_float4(0.f, 0.f, 0.f, 0.f);
        float* p = sA + r * SA_STRIDE + c4;
        p[0] = __uint_as_float(cvt_tf32(v.x));
        p[1] = __uint_as_float(cvt_tf32(v.y));
        p[2] = __uint_as_float(cvt_tf32(v.z));
        p[3] = __uint_as_float(cvt_tf32(v.w));
    }
    __syncthreads();

    int rbase = warp * 16;
    const float* pa0 = sA + (rbase + g) * SA_STRIDE;
    const float* pa1 = sA + (rbase + g + 8) * SA_STRIDE;

    float acc[16][4];
#pragma unroll
    for (int nt = 0; nt < 16; nt++)
#pragma unroll
        for (int j = 0; j < 4; j++) acc[nt][j] = 0.f;

#pragma unroll
    for (int kt = 0; kt < 16; kt++) {
        int k0 = kt * 8;
        unsigned a0 = __float_as_uint(pa0[k0 + t]);
        unsigned a1 = __float_as_uint(pa1[k0 + t]);
        unsigned a2 = __float_as_uint(pa0[k0 + t + 4]);
        unsigned a3 = __float_as_uint(pa1[k0 + t + 4]);
#pragma unroll
        for (int nt = 0; nt < 16; nt++) {
            const float* pb = sB + (nt * 8 + g) * SA_STRIDE + k0;
            unsigned b0 = __float_as_uint(pb[t]);
            unsigned b1 = __float_as_uint(pb[t + 4]);
            asm volatile(
                "mma.sync.aligned.m16n8k8.row.col.f32.tf32.tf32.f32 "
                "{%0,%1,%2,%3}, {%4,%5,%6,%7}, {%8,%9}, {%0,%1,%2,%3};"
                : "+f"(acc[nt][0]), "+f"(acc[nt][1]), "+f"(acc[nt][2]), "+f"(acc[nt][3])
                : "r"(a0), "r"(a1), "r"(a2), "r"(a3), "r"(b0), "r"(b1));
        }
    }

    // Epilogue: store xw rows (c0,c1 -> row g; c2,c3 -> row g+8; cols 2t,2t+1)
    int row0 = row0g + rbase + g;
    int row1 = row0 + 8;
#pragma unroll
    for (int nt = 0; nt < 16; nt++) {
        int col = nt * 8 + 2 * t;
        if (row0 < n)
            *(float2*)(g_xw + (size_t)row0 * 128 + col) = make_float2(acc[nt][0], acc[nt][1]);
        if (row1 < n)
            *(float2*)(g_xw + (size_t)row1 * 128 + col) = make_float2(acc[nt][2], acc[nt][3]);
    }

    // Fused attention dots: head h = cols [16h, 16h+16) = ntiles 2h, 2h+1.
#pragma unroll
    for (int h = 0; h < NH; h++) {
        float dt0 = 0.f, ds0 = 0.f, dt1 = 0.f, ds1 = 0.f;
#pragma unroll
        for (int j = 0; j < 2; j++) {
            int nt = 2 * h + j;
            int cw = j * 8 + 2 * t;        // col within head, 0..15
            float at0 = sAtt[h * 32 + cw],      at1 = sAtt[h * 32 + cw + 1];
            float as0 = sAtt[h * 32 + 16 + cw], as1 = sAtt[h * 32 + 16 + cw + 1];
            dt0 += acc[nt][0] * at0 + acc[nt][1] * at1;
            ds0 += acc[nt][0] * as0 + acc[nt][1] * as1;
            dt1 += acc[nt][2] * at0 + acc[nt][3] * at1;
            ds1 += acc[nt][2] * as0 + acc[nt][3] * as1;
        }
        // reduce across the quad (t = 0..3)
        dt0 += __shfl_xor_sync(0xffffffff, dt0, 1); dt0 += __shfl_xor_sync(0xffffffff, dt0, 2);
        ds0 += __shfl_xor_sync(0xffffffff, ds0, 1); ds0 += __shfl_xor_sync(0xffffffff, ds0, 2);
        dt1 += __shfl_xor_sync(0xffffffff, dt1, 1); dt1 += __shfl_xor_sync(0xffffffff, dt1, 2);
        ds1 += __shfl_xor_sync(0xffffffff, ds1, 1); ds1 += __shfl_xor_sync(0xffffffff, ds1, 2);
        if (t == 0) {
            if (row0 < n) { g_atgt[row0 * NH + h] = dt0; g_asrc[row0 * NH + h] = ds0; }
            if (row1 < n) { g_atgt[row1 * NH + h] = dt1; g_asrc[row1 * NH + h] = ds1; }
        }
    }
}

// ---------------------------------------------------------------------------
// K2: init — zero out (float4), denom=0.
// ---------------------------------------------------------------------------
__global__ void k_init(float* __restrict__ out, int n) {
    int i = blockIdx.x * blockDim.x + threadIdx.x;
    int total4 = n * 32;
    if (i < total4) ((float4*)out)[i] = make_float4(0.f, 0.f, 0.f, 0.f);
    if (i < n * NH) g_denom[i] = 0.f;
}

__device__ __forceinline__ int edge_at(const int* ei32, int idx, int shift) {
    return ei32[idx << shift];
}

__device__ __forceinline__ void red_add_v4(float* p, float a, float b, float c, float d) {
    asm volatile("red.global.add.v4.f32 [%0], {%1, %2, %3, %4};"
                 :: "l"(p), "f"(a), "f"(b), "f"(c), "f"(d) : "memory");
}

// ---------------------------------------------------------------------------
// K5: exp + denom + weighted scatter. One thread per (edge, head), 16 chans.
// No max subtraction (logits O(10); softmax shift-invariant).
// ---------------------------------------------------------------------------
__global__ void k_scatter(const int* __restrict__ ei32, float* __restrict__ out, int E) {
    int i = blockIdx.x * blockDim.x + threadIdx.x;
    if (i >= E * NH) return;
    int sh = g_is64;
    int e = i >> 3, h = i & 7;
    int s = edge_at(ei32, e, sh);
    int d = edge_at(ei32, E + e, sh);
    int dh = d * NH + h;
    float a = g_atgt[dh] + g_asrc[s * NH + h];
    a = a > 0.f ? a : 0.2f * a;
    float ex = __expf(a);
    atomicAdd(&g_denom[dh], ex);
    const float4* xs = (const float4*)(g_xw + (size_t)s * 128 + h * 16);
    float* op = out + (size_t)d * 128 + h * 16;
#pragma unroll
    for (int j = 0; j < 4; j++) {
        float4 v = xs[j];
        red_add_v4(op + j * 4, ex * v.x, ex * v.y, ex * v.z, ex * v.w);
    }
}

// ---------------------------------------------------------------------------
// K6: normalize by denom, add bias.
// ---------------------------------------------------------------------------
__global__ void k_final(float* __restrict__ out, const float* __restrict__ bias, int n) {
    int i = blockIdx.x * blockDim.x + threadIdx.x;
    if (i >= n * 32) return;
    int node = i >> 5;
    int q = i & 31;
    int h = q >> 2;
    float inv = 1.f / g_denom[node * NH + h];
    float4 v = ((float4*)out)[i];
    float4 b = ((const float4*)bias)[q];
    v.x = v.x * inv + b.x;
    v.y = v.y * inv + b.y;
    v.z = v.z * inv + b.z;
    v.w = v.w * inv + b.w;
    ((float4*)out)[i] = v;
}

// ---------------------------------------------------------------------------
extern "C" void kernel_launch(void* const* d_in, const int* in_sizes, int n_in,
                              void* d_out, int out_size) {
    int order[16];
    for (int i = 0; i < n_in; i++) order[i] = i;
    for (int a = 0; a < n_in; a++)
        for (int b = a + 1; b < n_in; b++)
            if (in_sizes[order[b]] > in_sizes[order[a]]) {
                int t = order[a]; order[a] = order[b]; order[b] = t;
            }
    const float* x    = (const float*)d_in[order[0]];
    const int*   ei32 = (const int*)  d_in[order[1]];
    const float* w    = (const float*)d_in[order[3]];
    const float* att  = (const float*)d_in[order[4]];
    const float* bias = (const float*)d_in[order[5]];
    float*       out  = (float*)d_out;

    int n = in_sizes[order[0]] / 128;  // num nodes
    int E = in_sizes[order[1]] / 2;    // num edges (incl. self-loops)

    k_detect<<<1, 32>>>(ei32, E);

    int smem_bytes = (2 * 128 * SA_STRIDE + 256) * sizeof(float);
    cudaFuncSetAttribute(k_gemm_tf32, cudaFuncAttributeMaxDynamicSharedMemorySize, smem_bytes);
    k_gemm_tf32<<<(n + 127) / 128, 256, smem_bytes>>>(x, w, att, n);

    int t4 = n * 32;
    k_init<<<(t4 + 255) / 256, 256>>>(out, n);

    int teh = E * NH;
    k_scatter<<<(teh + 255) / 256, 256>>>(ei32, out, E);

    k_final<<<(t4 + 255) / 256, 256>>>(out, bias, n);
}

// round 6
// speedup vs baseline: 3.5822x; 1.3098x over previous
#include <cuda_runtime.h>
#include <math_constants.h>

#define MAXN 100000
#define MAXE 720000
#define NH   8
#define HC   128

__device__ float g_xw[MAXN * HC];     // x @ W            [N, H*C]
__device__ float g_atgt[MAXN * NH];   // dot(xw, att[:, :C])
__device__ float g_asrc[MAXN * NH];   // dot(xw, att[:, C:])
__device__ int   g_deg[MAXN];         // per-dst degree
__device__ int   g_start[MAXN];       // CSR start offsets
__device__ int   g_cursor[MAXN];      // fill cursors
__device__ int   g_srcidx[MAXE];      // CSR: src node per edge, bucketed by dst
__device__ int   g_bsum[512];         // scan block sums
__device__ int   g_is64;

// ---------------------------------------------------------------------------
__global__ void k_detect(const int* __restrict__ ei32, int E) {
    if (threadIdx.x == 0 && blockIdx.x == 0) {
        int m = E < 128 ? E : 128;
        int nz = 0;
        for (int i = 0; i < m; i++) nz |= ei32[2 * i + 1];
        g_is64 = (nz == 0) ? 1 : 0;
    }
}

__device__ __forceinline__ int edge_at(const int* ei32, int idx, int shift) {
    return ei32[idx << shift];
}

__device__ __forceinline__ unsigned cvt_tf32(float f) {
    unsigned r;
    asm("cvt.rna.tf32.f32 %0, %1;" : "=r"(r) : "f"(f));
    return r;
}

// ---------------------------------------------------------------------------
// K1: tf32 tensor-core GEMM xw = x @ W (128x128 tile/block) + fused att dots.
// ---------------------------------------------------------------------------
#define SA_STRIDE 132
__global__ void __launch_bounds__(256) k_gemm_tf32(
        const float* __restrict__ x, const float* __restrict__ w,
        const float* __restrict__ att, int n) {
    extern __shared__ float smem[];
    float* sA   = smem;
    float* sB   = smem + 128 * SA_STRIDE;
    float* sAtt = smem + 2 * 128 * SA_STRIDE;

    int tid  = threadIdx.x;
    int lane = tid & 31, warp = tid >> 5;
    int g = lane >> 2, t = lane & 3;
    int row0g = blockIdx.x * 128;

    sAtt[tid] = att[tid];

#pragma unroll
    for (int i = 0; i < 16; i++) {
        int idx = tid + i * 256;
        float4 v = ((const float4*)w)[idx];
        int k  = idx >> 5;
        int n4 = (idx & 31) * 4;
        sB[(n4 + 0) * SA_STRIDE + k] = __uint_as_float(cvt_tf32(v.x));
        sB[(n4 + 1) * SA_STRIDE + k] = __uint_as_float(cvt_tf32(v.y));
        sB[(n4 + 2) * SA_STRIDE + k] = __uint_as_float(cvt_tf32(v.z));
        sB[(n4 + 3) * SA_STRIDE + k] = __uint_as_float(cvt_tf32(v.w));
    }

    const float4* x4 = (const float4*)(x + (size_t)row0g * 128);
#pragma unroll
    for (int i = 0; i < 16; i++) {
        int idx = tid + i * 256;
        int r  = idx >> 5;
        int c4 = (idx & 31) * 4;
        float4 v = (row0g + r < n) ? x4[idx] : make_float4(0.f, 0.f, 0.f, 0.f);
        float* p = sA + r * SA_STRIDE + c4;
        p[0] = __uint_as_float(cvt_tf32(v.x));
        p[1] = __uint_as_float(cvt_tf32(v.y));
        p[2] = __uint_as_float(cvt_tf32(v.z));
        p[3] = __uint_as_float(cvt_tf32(v.w));
    }
    __syncthreads();

    int rbase = warp * 16;
    const float* pa0 = sA + (rbase + g) * SA_STRIDE;
    const float* pa1 = sA + (rbase + g + 8) * SA_STRIDE;

    float acc[16][4];
#pragma unroll
    for (int nt = 0; nt < 16; nt++)
#pragma unroll
        for (int j = 0; j < 4; j++) acc[nt][j] = 0.f;

#pragma unroll
    for (int kt = 0; kt < 16; kt++) {
        int k0 = kt * 8;
        unsigned a0 = __float_as_uint(pa0[k0 + t]);
        unsigned a1 = __float_as_uint(pa1[k0 + t]);
        unsigned a2 = __float_as_uint(pa0[k0 + t + 4]);
        unsigned a3 = __float_as_uint(pa1[k0 + t + 4]);
#pragma unroll
        for (int nt = 0; nt < 16; nt++) {
            const float* pb = sB + (nt * 8 + g) * SA_STRIDE + k0;
            unsigned b0 = __float_as_uint(pb[t]);
            unsigned b1 = __float_as_uint(pb[t + 4]);
            asm volatile(
                "mma.sync.aligned.m16n8k8.row.col.f32.tf32.tf32.f32 "
                "{%0,%1,%2,%3}, {%4,%5,%6,%7}, {%8,%9}, {%0,%1,%2,%3};"
                : "+f"(acc[nt][0]), "+f"(acc[nt][1]), "+f"(acc[nt][2]), "+f"(acc[nt][3])
                : "r"(a0), "r"(a1), "r"(a2), "r"(a3), "r"(b0), "r"(b1));
        }
    }

    int row0 = row0g + rbase + g;
    int row1 = row0 + 8;
#pragma unroll
    for (int nt = 0; nt < 16; nt++) {
        int col = nt * 8 + 2 * t;
        if (row0 < n)
            *(float2*)(g_xw + (size_t)row0 * 128 + col) = make_float2(acc[nt][0], acc[nt][1]);
        if (row1 < n)
            *(float2*)(g_xw + (size_t)row1 * 128 + col) = make_float2(acc[nt][2], acc[nt][3]);
    }

#pragma unroll
    for (int h = 0; h < NH; h++) {
        float dt0 = 0.f, ds0 = 0.f, dt1 = 0.f, ds1 = 0.f;
#pragma unroll
        for (int j = 0; j < 2; j++) {
            int nt = 2 * h + j;
            int cw = j * 8 + 2 * t;
            float at0 = sAtt[h * 32 + cw],      at1 = sAtt[h * 32 + cw + 1];
            float as0 = sAtt[h * 32 + 16 + cw], as1 = sAtt[h * 32 + 16 + cw + 1];
            dt0 += acc[nt][0] * at0 + acc[nt][1] * at1;
            ds0 += acc[nt][0] * as0 + acc[nt][1] * as1;
            dt1 += acc[nt][2] * at0 + acc[nt][3] * at1;
            ds1 += acc[nt][2] * as0 + acc[nt][3] * as1;
        }
        dt0 += __shfl_xor_sync(0xffffffff, dt0, 1); dt0 += __shfl_xor_sync(0xffffffff, dt0, 2);
        ds0 += __shfl_xor_sync(0xffffffff, ds0, 1); ds0 += __shfl_xor_sync(0xffffffff, ds0, 2);
        dt1 += __shfl_xor_sync(0xffffffff, dt1, 1); dt1 += __shfl_xor_sync(0xffffffff, dt1, 2);
        ds1 += __shfl_xor_sync(0xffffffff, ds1, 1); ds1 += __shfl_xor_sync(0xffffffff, ds1, 2);
        if (t == 0) {
            if (row0 < n) { g_atgt[row0 * NH + h] = dt0; g_asrc[row0 * NH + h] = ds0; }
            if (row1 < n) { g_atgt[row1 * NH + h] = dt1; g_asrc[row1 * NH + h] = ds1; }
        }
    }
}

// ---------------------------------------------------------------------------
// CSR build: zero degrees -> histogram -> 3-phase exclusive scan -> permute
// ---------------------------------------------------------------------------
__global__ void k_zero_deg(int n) {
    int i = blockIdx.x * blockDim.x + threadIdx.x;
    if (i < n) g_deg[i] = 0;
}

__global__ void k_hist(const int* __restrict__ ei32, int E) {
    int i = blockIdx.x * blockDim.x + threadIdx.x;
    if (i >= E) return;
    int d = edge_at(ei32, E + i, g_is64);
    atomicAdd(&g_deg[d], 1);
}

// scan phase 1: per-block (256) exclusive scan + block total
__global__ void k_scan1(int n) {
    int i = blockIdx.x * 256 + threadIdx.x;
    int lane = threadIdx.x & 31, w = threadIdx.x >> 5;
    int v = (i < n) ? g_deg[i] : 0;
    int x = v;
#pragma unroll
    for (int o = 1; o < 32; o <<= 1) {
        int y = __shfl_up_sync(0xffffffff, x, o);
        if (lane >= o) x += y;
    }
    __shared__ int wsum[8];
    if (lane == 31) wsum[w] = x;
    __syncthreads();
    if (threadIdx.x < 8) {
        int s = wsum[threadIdx.x];
#pragma unroll
        for (int o = 1; o < 8; o <<= 1) {
            int y = __shfl_up_sync(0xff, s, o);
            if ((int)threadIdx.x >= o) s += y;
        }
        wsum[threadIdx.x] = s;
    }
    __syncthreads();
    int base = (w > 0) ? wsum[w - 1] : 0;
    if (i < n) g_start[i] = base + x - v;
    if (threadIdx.x == 0) g_bsum[blockIdx.x] = wsum[7];
}

// scan phase 2: single block (512 threads) exclusive-scans block sums in place
__global__ void k_scan2(int nb) {
    int i = threadIdx.x;               // 0..511
    int lane = i & 31, w = i >> 5;
    int v = (i < nb) ? g_bsum[i] : 0;
    int x = v;
#pragma unroll
    for (int o = 1; o < 32; o <<= 1) {
        int y = __shfl_up_sync(0xffffffff, x, o);
        if (lane >= o) x += y;
    }
    __shared__ int wsum[16];
    if (lane == 31) wsum[w] = x;
    __syncthreads();
    if (i < 16) {
        int s = wsum[i];
#pragma unroll
        for (int o = 1; o < 16; o <<= 1) {
            int y = __shfl_up_sync(0xffff, s, o);
            if (i >= o) s += y;
        }
        wsum[i] = s;
    }
    __syncthreads();
    int base = (w > 0) ? wsum[w - 1] : 0;
    if (i < nb) g_bsum[i] = base + x - v;   // exclusive block offset
}

// scan phase 3: add block offsets, init cursors
__global__ void k_scan3(int n) {
    int i = blockIdx.x * 256 + threadIdx.x;
    if (i >= n) return;
    int s = g_start[i] + g_bsum[blockIdx.x];
    g_start[i] = s;
    g_cursor[i] = s;
}

__global__ void k_permute(const int* __restrict__ ei32, int E) {
    int i = blockIdx.x * blockDim.x + threadIdx.x;
    if (i >= E) return;
    int sh = g_is64;
    int s = edge_at(ei32, i, sh);
    int d = edge_at(ei32, E + i, sh);
    int pos = atomicAdd(&g_cursor[d], 1);
    g_srcidx[pos] = s;
}

// ---------------------------------------------------------------------------
// K5: gather — one warp per dst node. Accumulates msg (float4/thread) and
// softmax denom in registers; applies 1/denom and bias; single 512B store.
// No atomics, no out init, no final pass. exp on lanes 0-7 only, shfl bcast.
// ---------------------------------------------------------------------------
__global__ void __launch_bounds__(256) k_gather(float* __restrict__ out,
                                                const float* __restrict__ bias, int n) {
    int gw = (blockIdx.x * blockDim.x + threadIdx.x) >> 5;
    if (gw >= n) return;
    int lane = threadIdx.x & 31;
    int d = gw;
    int hl = lane & 7;
    float atgtv = g_atgt[d * NH + hl];
    int start = g_start[d], deg = g_deg[d];
    float4 acc = make_float4(0.f, 0.f, 0.f, 0.f);
    float den = 0.f;
    const float4* xw4 = (const float4*)g_xw;

    int sn = (deg > 0) ? g_srcidx[start] : 0;
    for (int j = 0; j < deg; j++) {
        int s = sn;
        if (j + 1 < deg) sn = g_srcidx[start + j + 1];   // prefetch next
        float a = atgtv + g_asrc[s * NH + hl];
        a = a > 0.f ? a : 0.2f * a;
        float ex = 0.f;
        if (lane < 8) ex = __expf(a);
        float exv = __shfl_sync(0xffffffff, ex, lane >> 2);
        float4 v = xw4[(size_t)s * 32 + lane];
        acc.x += exv * v.x; acc.y += exv * v.y;
        acc.z += exv * v.z; acc.w += exv * v.w;
        den += exv;
    }
    float inv = 1.f / den;    // deg >= 1 (self-loops)
    float4 b = ((const float4*)bias)[lane];
    float4 o;
    o.x = acc.x * inv + b.x; o.y = acc.y * inv + b.y;
    o.z = acc.z * inv + b.z; o.w = acc.w * inv + b.w;
    ((float4*)out)[(size_t)d * 32 + lane] = o;
}

// ---------------------------------------------------------------------------
extern "C" void kernel_launch(void* const* d_in, const int* in_sizes, int n_in,
                              void* d_out, int out_size) {
    int order[16];
    for (int i = 0; i < n_in; i++) order[i] = i;
    for (int a = 0; a < n_in; a++)
        for (int b = a + 1; b < n_in; b++)
            if (in_sizes[order[b]] > in_sizes[order[a]]) {
                int t = order[a]; order[a] = order[b]; order[b] = t;
            }
    const float* x    = (const float*)d_in[order[0]];
    const int*   ei32 = (const int*)  d_in[order[1]];
    const float* w    = (const float*)d_in[order[3]];
    const float* att  = (const float*)d_in[order[4]];
    const float* bias = (const float*)d_in[order[5]];
    float*       out  = (float*)d_out;

    int n = in_sizes[order[0]] / 128;  // num nodes
    int E = in_sizes[order[1]] / 2;    // num edges (incl. self-loops)

    k_detect<<<1, 32>>>(ei32, E);

    int smem_bytes = (2 * 128 * SA_STRIDE + 256) * sizeof(float);
    cudaFuncSetAttribute(k_gemm_tf32, cudaFuncAttributeMaxDynamicSharedMemorySize, smem_bytes);
    k_gemm_tf32<<<(n + 127) / 128, 256, smem_bytes>>>(x, w, att, n);

    int nb = (n + 255) / 256;
    k_zero_deg<<<nb, 256>>>(n);
    k_hist<<<(E + 255) / 256, 256>>>(ei32, E);
    k_scan1<<<nb, 256>>>(n);
    k_scan2<<<1, 512>>>(nb);
    k_scan3<<<nb, 256>>>(n);
    k_permute<<<(E + 255) / 256, 256>>>(ei32, E);

    k_gather<<<(n * 32 + 255) / 256, 256>>>(out, bias, n);
}

// round 7
// speedup vs baseline: 4.4277x; 1.2360x over previous
#include <cuda_runtime.h>
#include <math_constants.h>

#define MAXN 100000
#define MAXE 720000
#define NH   8
#define HC   128

__device__ float g_xw[MAXN * HC];     // x @ W  [N, H*C]
__device__ float g_atgt[MAXN * NH];
__device__ float g_asrc[MAXN * NH];
__device__ float g_wt[HC * HC];       // W^T, tf32-rounded bits, [n][k]
__device__ int   g_deg[MAXN];
__device__ int   g_start[MAXN];       // start; after permute holds end
__device__ int   g_srcidx[MAXE];
__device__ int   g_bsum[512];
__device__ int   g_is64;

__device__ __forceinline__ unsigned cvt_tf32(float f) {
    unsigned r;
    asm("cvt.rna.tf32.f32 %0, %1;" : "=r"(r) : "f"(f));
    return r;
}

__device__ __forceinline__ int edge_at(const int* ei32, int idx, int shift) {
    return ei32[idx << shift];
}

// ---------------------------------------------------------------------------
// K_prep: zero degrees + detect edge dtype + precompute W^T (tf32) once.
// ---------------------------------------------------------------------------
__global__ void k_prep(const int* __restrict__ ei32, const float* __restrict__ w,
                       int n, int E) {
    int i = blockIdx.x * blockDim.x + threadIdx.x;
    if (i < n) g_deg[i] = 0;
    if (i < HC * HC) {
        int k = i >> 7, nn = i & 127;          // read w[k][n] coalesced
        g_wt[nn * HC + k] = __uint_as_float(cvt_tf32(w[i]));
    }
    if (i == 0) {
        int m = E < 128 ? E : 128;
        int nz = 0;
        for (int j = 0; j < m; j++) nz |= ei32[2 * j + 1];
        g_is64 = (nz == 0) ? 1 : 0;
    }
}

// ---------------------------------------------------------------------------
// K1: tf32 tensor-core GEMM xw = x @ W (128x128 tile/block) + fused att dots.
// ---------------------------------------------------------------------------
#define SA_STRIDE 132
__global__ void __launch_bounds__(256) k_gemm_tf32(
        const float* __restrict__ x, const float* __restrict__ att, int n) {
    extern __shared__ float smem[];
    float* sA   = smem;
    float* sB   = smem + 128 * SA_STRIDE;
    float* sAtt = smem + 2 * 128 * SA_STRIDE;

    int tid  = threadIdx.x;
    int lane = tid & 31, warp = tid >> 5;
    int g = lane >> 2, t = lane & 3;
    int row0g = blockIdx.x * 128;

    sAtt[tid] = att[tid];

    // sB <- g_wt (already tf32 bits, [n][k] layout), float4 copy.
    const float4* wt4 = (const float4*)g_wt;
#pragma unroll
    for (int i = 0; i < 16; i++) {
        int idx = tid + i * 256;
        int nn = idx >> 5, k4 = (idx & 31) * 4;
        *(float4*)(sB + nn * SA_STRIDE + k4) = wt4[idx];
    }

    const float4* x4 = (const float4*)(x + (size_t)row0g * 128);
#pragma unroll
    for (int i = 0; i < 16; i++) {
        int idx = tid + i * 256;
        int r  = idx >> 5;
        int c4 = (idx & 31) * 4;
        float4 v = (row0g + r < n) ? x4[idx] : make_float4(0.f, 0.f, 0.f, 0.f);
        float4 c;
        c.x = __uint_as_float(cvt_tf32(v.x));
        c.y = __uint_as_float(cvt_tf32(v.y));
        c.z = __uint_as_float(cvt_tf32(v.z));
        c.w = __uint_as_float(cvt_tf32(v.w));
        *(float4*)(sA + r * SA_STRIDE + c4) = c;
    }
    __syncthreads();

    int rbase = warp * 16;
    const float* pa0 = sA + (rbase + g) * SA_STRIDE;
    const float* pa1 = sA + (rbase + g + 8) * SA_STRIDE;

    float acc[16][4];
#pragma unroll
    for (int nt = 0; nt < 16; nt++)
#pragma unroll
        for (int j = 0; j < 4; j++) acc[nt][j] = 0.f;

#pragma unroll
    for (int kt = 0; kt < 16; kt++) {
        int k0 = kt * 8;
        unsigned a0 = __float_as_uint(pa0[k0 + t]);
        unsigned a1 = __float_as_uint(pa1[k0 + t]);
        unsigned a2 = __float_as_uint(pa0[k0 + t + 4]);
        unsigned a3 = __float_as_uint(pa1[k0 + t + 4]);
#pragma unroll
        for (int nt = 0; nt < 16; nt++) {
            const float* pb = sB + (nt * 8 + g) * SA_STRIDE + k0;
            unsigned b0 = __float_as_uint(pb[t]);
            unsigned b1 = __float_as_uint(pb[t + 4]);
            asm volatile(
                "mma.sync.aligned.m16n8k8.row.col.f32.tf32.tf32.f32 "
                "{%0,%1,%2,%3}, {%4,%5,%6,%7}, {%8,%9}, {%0,%1,%2,%3};"
                : "+f"(acc[nt][0]), "+f"(acc[nt][1]), "+f"(acc[nt][2]), "+f"(acc[nt][3])
                : "r"(a0), "r"(a1), "r"(a2), "r"(a3), "r"(b0), "r"(b1));
        }
    }

    int row0 = row0g + rbase + g;
    int row1 = row0 + 8;
#pragma unroll
    for (int nt = 0; nt < 16; nt++) {
        int col = nt * 8 + 2 * t;
        if (row0 < n)
            *(float2*)(g_xw + (size_t)row0 * 128 + col) = make_float2(acc[nt][0], acc[nt][1]);
        if (row1 < n)
            *(float2*)(g_xw + (size_t)row1 * 128 + col) = make_float2(acc[nt][2], acc[nt][3]);
    }

#pragma unroll
    for (int h = 0; h < NH; h++) {
        float dt0 = 0.f, ds0 = 0.f, dt1 = 0.f, ds1 = 0.f;
#pragma unroll
        for (int j = 0; j < 2; j++) {
            int nt = 2 * h + j;
            int cw = j * 8 + 2 * t;
            float at0 = sAtt[h * 32 + cw],      at1 = sAtt[h * 32 + cw + 1];
            float as0 = sAtt[h * 32 + 16 + cw], as1 = sAtt[h * 32 + 16 + cw + 1];
            dt0 += acc[nt][0] * at0 + acc[nt][1] * at1;
            ds0 += acc[nt][0] * as0 + acc[nt][1] * as1;
            dt1 += acc[nt][2] * at0 + acc[nt][3] * at1;
            ds1 += acc[nt][2] * as0 + acc[nt][3] * as1;
        }
        dt0 += __shfl_xor_sync(0xffffffff, dt0, 1); dt0 += __shfl_xor_sync(0xffffffff, dt0, 2);
        ds0 += __shfl_xor_sync(0xffffffff, ds0, 1); ds0 += __shfl_xor_sync(0xffffffff, ds0, 2);
        dt1 += __shfl_xor_sync(0xffffffff, dt1, 1); dt1 += __shfl_xor_sync(0xffffffff, dt1, 2);
        ds1 += __shfl_xor_sync(0xffffffff, ds1, 1); ds1 += __shfl_xor_sync(0xffffffff, ds1, 2);
        if (t == 0) {
            if (row0 < n) { g_atgt[row0 * NH + h] = dt0; g_asrc[row0 * NH + h] = ds0; }
            if (row1 < n) { g_atgt[row1 * NH + h] = dt1; g_asrc[row1 * NH + h] = ds1; }
        }
    }
}

// ---------------------------------------------------------------------------
// CSR build: histogram -> 3-phase exclusive scan -> permute (cursor = g_start)
// ---------------------------------------------------------------------------
__global__ void k_hist(const int* __restrict__ ei32, int E) {
    int i = blockIdx.x * blockDim.x + threadIdx.x;
    if (i >= E) return;
    int d = edge_at(ei32, E + i, g_is64);
    atomicAdd(&g_deg[d], 1);
}

__global__ void k_scan1(int n) {
    int i = blockIdx.x * 256 + threadIdx.x;
    int lane = threadIdx.x & 31, w = threadIdx.x >> 5;
    int v = (i < n) ? g_deg[i] : 0;
    int x = v;
#pragma unroll
    for (int o = 1; o < 32; o <<= 1) {
        int y = __shfl_up_sync(0xffffffff, x, o);
        if (lane >= o) x += y;
    }
    __shared__ int wsum[8];
    if (lane == 31) wsum[w] = x;
    __syncthreads();
    if (threadIdx.x < 8) {
        int s = wsum[threadIdx.x];
#pragma unroll
        for (int o = 1; o < 8; o <<= 1) {
            int y = __shfl_up_sync(0xff, s, o);
            if ((int)threadIdx.x >= o) s += y;
        }
        wsum[threadIdx.x] = s;
    }
    __syncthreads();
    int base = (w > 0) ? wsum[w - 1] : 0;
    if (i < n) g_start[i] = base + x - v;
    if (threadIdx.x == 0) g_bsum[blockIdx.x] = wsum[7];
}

__global__ void k_scan2(int nb) {
    int i = threadIdx.x;
    int lane = i & 31, w = i >> 5;
    int v = (i < nb) ? g_bsum[i] : 0;
    int x = v;
#pragma unroll
    for (int o = 1; o < 32; o <<= 1) {
        int y = __shfl_up_sync(0xffffffff, x, o);
        if (lane >= o) x += y;
    }
    __shared__ int wsum[16];
    if (lane == 31) wsum[w] = x;
    __syncthreads();
    if (i < 16) {
        int s = wsum[i];
#pragma unroll
        for (int o = 1; o < 16; o <<= 1) {
            int y = __shfl_up_sync(0xffff, s, o);
            if (i >= o) s += y;
        }
        wsum[i] = s;
    }
    __syncthreads();
    int base = (w > 0) ? wsum[w - 1] : 0;
    if (i < nb) g_bsum[i] = base + x - v;
}

__global__ void k_scan3(int n) {
    int i = blockIdx.x * 256 + threadIdx.x;
    if (i < n) g_start[i] += g_bsum[blockIdx.x];
}

__global__ void k_permute(const int* __restrict__ ei32, int E) {
    int i = blockIdx.x * blockDim.x + threadIdx.x;
    if (i >= E) return;
    int sh = g_is64;
    int s = edge_at(ei32, i, sh);
    int d = edge_at(ei32, E + i, sh);
    int pos = atomicAdd(&g_start[d], 1);   // g_start becomes end-of-bucket
    g_srcidx[pos] = s;
}

// ---------------------------------------------------------------------------
// K5: gather — one warp per dst node, fully software-pipelined.
// Lane L handles channels [4L, 4L+4) => head h = L>>2. All lanes exp (MUFU is
// warp-wide), no shuffles. srcidx/asrc/xw prefetched one edge ahead.
// ---------------------------------------------------------------------------
__global__ void __launch_bounds__(256) k_gather(float* __restrict__ out,
                                                const float* __restrict__ bias, int n) {
    int gw = (blockIdx.x * blockDim.x + threadIdx.x) >> 5;
    if (gw >= n) return;
    int lane = threadIdx.x & 31;
    int d = gw;
    int h = lane >> 2;
    float atgtv = g_atgt[d * NH + h];
    int deg = g_deg[d];
    int start = g_start[d] - deg;          // g_start holds end after permute
    float4 acc = make_float4(0.f, 0.f, 0.f, 0.f);
    float den = 0.f;
    const float4* xw4 = (const float4*)g_xw;

    if (deg > 0) {
        int s_n = g_srcidx[start];
        float as_n = g_asrc[s_n * NH + h];
        float4 v_n = __ldg(xw4 + (size_t)s_n * 32 + lane);
        for (int j = 0; j < deg; j++) {
            float as = as_n;
            float4 v = v_n;
            if (j + 1 < deg) {
                int s2 = g_srcidx[start + j + 1];
                as_n = g_asrc[s2 * NH + h];
                v_n = __ldg(xw4 + (size_t)s2 * 32 + lane);
            }
            float a = atgtv + as;
            a = a > 0.f ? a : 0.2f * a;
            float ex = __expf(a);
            acc.x += ex * v.x; acc.y += ex * v.y;
            acc.z += ex * v.z; acc.w += ex * v.w;
            den += ex;
        }
    }
    float inv = (den > 0.f) ? 1.f / den : 0.f;
    float4 b = ((const float4*)bias)[lane];
    float4 o;
    o.x = acc.x * inv + b.x; o.y = acc.y * inv + b.y;
    o.z = acc.z * inv + b.z; o.w = acc.w * inv + b.w;
    ((float4*)out)[(size_t)d * 32 + lane] = o;
}

// ---------------------------------------------------------------------------
extern "C" void kernel_launch(void* const* d_in, const int* in_sizes, int n_in,
                              void* d_out, int out_size) {
    int order[16];
    for (int i = 0; i < n_in; i++) order[i] = i;
    for (int a = 0; a < n_in; a++)
        for (int b = a + 1; b < n_in; b++)
            if (in_sizes[order[b]] > in_sizes[order[a]]) {
                int t = order[a]; order[a] = order[b]; order[b] = t;
            }
    const float* x    = (const float*)d_in[order[0]];
    const int*   ei32 = (const int*)  d_in[order[1]];
    // order[2] = mask (unused)
    // order[3] = weight
    const float* w    = (const float*)d_in[order[3]];
    const float* att  = (const float*)d_in[order[4]];
    const float* bias = (const float*)d_in[order[5]];
    float*       out  = (float*)d_out;

    int n = in_sizes[order[0]] / 128;
    int E = in_sizes[order[1]] / 2;

    // persistent fork stream + events (handles only; created once, outside capture)
    static cudaStream_t s2 = nullptr;
    static cudaEvent_t evFork = nullptr, evJoin = nullptr;
    if (!s2) {
        cudaStreamCreateWithFlags(&s2, cudaStreamNonBlocking);
        cudaEventCreateWithFlags(&evFork, cudaEventDisableTiming);
        cudaEventCreateWithFlags(&evJoin, cudaEventDisableTiming);
    }

    int nb = (n + 255) / 256;

    k_prep<<<nb, 256>>>(ei32, w, n, E);

    // fork: CSR build on s2, GEMM on main stream — independent work
    cudaEventRecord(evFork, 0);
    cudaStreamWaitEvent(s2, evFork, 0);

    int smem_bytes = (2 * 128 * SA_STRIDE + 256) * sizeof(float);
    cudaFuncSetAttribute(k_gemm_tf32, cudaFuncAttributeMaxDynamicSharedMemorySize, smem_bytes);
    k_gemm_tf32<<<(n + 127) / 128, 256, smem_bytes>>>(x, att, n);

    k_hist<<<(E + 255) / 256, 256, 0, s2>>>(ei32, E);
    k_scan1<<<nb, 256, 0, s2>>>(n);
    k_scan2<<<1, 512, 0, s2>>>(nb);
    k_scan3<<<nb, 256, 0, s2>>>(n);
    k_permute<<<(E + 255) / 256, 256, 0, s2>>>(ei32, E);

    // join
    cudaEventRecord(evJoin, s2);
    cudaStreamWaitEvent(0, evJoin, 0);

    k_gather<<<(n * 32 + 255) / 256, 256>>>(out, bias, n);
}

// round 10
// speedup vs baseline: 5.0525x; 1.1411x over previous
#include <cuda_runtime.h>
#include <cuda_fp16.h>
#include <math_constants.h>

#define MAXN 100000
#define MAXE 720000
#define NH   8
#define HC   128

__device__ __half g_xwh[MAXN * HC];   // x @ W, fp16 for gather  [N, H*C]
__device__ float  g_atgt[MAXN * NH];
__device__ float  g_asrc[MAXN * NH];
__device__ float  g_wt[HC * HC];      // W^T, tf32-rounded bits, [n][k]
__device__ int    g_deg[MAXN];
__device__ int    g_start[MAXN];      // start; after permute holds end
__device__ int    g_srcidx[MAXE];
__device__ int    g_bsum[512];
__device__ int    g_is64;

__device__ __forceinline__ unsigned cvt_tf32(float f) {
    unsigned r;
    asm("cvt.rna.tf32.f32 %0, %1;" : "=r"(r) : "f"(f));
    return r;
}

__device__ __forceinline__ int edge_at(const int* ei32, int idx, int shift) {
    return ei32[idx << shift];
}

// ---------------------------------------------------------------------------
// K_prepW (main stream): W^T tf32 precompute — feeds the GEMM.
// ---------------------------------------------------------------------------
__global__ void k_prep_w(const float* __restrict__ w) {
    int i = blockIdx.x * blockDim.x + threadIdx.x;   // 16384 threads
    int k = i >> 7, nn = i & 127;
    g_wt[nn * HC + k] = __uint_as_float(cvt_tf32(w[i]));
}

// ---------------------------------------------------------------------------
// K_prepE (stream 2): zero degrees + detect edge dtype — feeds hist.
// ---------------------------------------------------------------------------
__global__ void k_prep_e(const int* __restrict__ ei32, int n, int E) {
    int i = blockIdx.x * blockDim.x + threadIdx.x;
    if (i < n) g_deg[i] = 0;
    if (i == 0) {
        int m = E < 128 ? E : 128;
        int nz = 0;
        for (int j = 0; j < m; j++) nz |= ei32[2 * j + 1];
        g_is64 = (nz == 0) ? 1 : 0;
    }
}

// ---------------------------------------------------------------------------
// K1: tf32 tensor-core GEMM xw = x @ W (128x128 tile/block) + fused att dots.
// Epilogue stores xw as fp16 (halves gather traffic).
// ---------------------------------------------------------------------------
#define SA_STRIDE 132
__global__ void __launch_bounds__(256) k_gemm_tf32(
        const float* __restrict__ x, const float* __restrict__ att, int n) {
    extern __shared__ float smem[];
    float* sA   = smem;
    float* sB   = smem + 128 * SA_STRIDE;
    float* sAtt = smem + 2 * 128 * SA_STRIDE;

    int tid  = threadIdx.x;
    int lane = tid & 31, warp = tid >> 5;
    int g = lane >> 2, t = lane & 3;
    int row0g = blockIdx.x * 128;

    sAtt[tid] = att[tid];

    const float4* wt4 = (const float4*)g_wt;
#pragma unroll
    for (int i = 0; i < 16; i++) {
        int idx = tid + i * 256;
        int nn = idx >> 5, k4 = (idx & 31) * 4;
        *(float4*)(sB + nn * SA_STRIDE + k4) = wt4[idx];
    }

    const float4* x4 = (const float4*)(x + (size_t)row0g * 128);
#pragma unroll
    for (int i = 0; i < 16; i++) {
        int idx = tid + i * 256;
        int r  = idx >> 5;
        int c4 = (idx & 31) * 4;
        float4 v = (row0g + r < n) ? x4[idx] : make_float4(0.f, 0.f, 0.f, 0.f);
        float4 c;
        c.x = __uint_as_float(cvt_tf32(v.x));
        c.y = __uint_as_float(cvt_tf32(v.y));
        c.z = __uint_as_float(cvt_tf32(v.z));
        c.w = __uint_as_float(cvt_tf32(v.w));
        *(float4*)(sA + r * SA_STRIDE + c4) = c;
    }
    __syncthreads();

    int rbase = warp * 16;
    const float* pa0 = sA + (rbase + g) * SA_STRIDE;
    const float* pa1 = sA + (rbase + g + 8) * SA_STRIDE;

    float acc[16][4];
#pragma unroll
    for (int nt = 0; nt < 16; nt++)
#pragma unroll
        for (int j = 0; j < 4; j++) acc[nt][j] = 0.f;

#pragma unroll
    for (int kt = 0; kt < 16; kt++) {
        int k0 = kt * 8;
        unsigned a0 = __float_as_uint(pa0[k0 + t]);
        unsigned a1 = __float_as_uint(pa1[k0 + t]);
        unsigned a2 = __float_as_uint(pa0[k0 + t + 4]);
        unsigned a3 = __float_as_uint(pa1[k0 + t + 4]);
#pragma unroll
        for (int nt = 0; nt < 16; nt++) {
            const float* pb = sB + (nt * 8 + g) * SA_STRIDE + k0;
            unsigned b0 = __float_as_uint(pb[t]);
            unsigned b1 = __float_as_uint(pb[t + 4]);
            asm volatile(
                "mma.sync.aligned.m16n8k8.row.col.f32.tf32.tf32.f32 "
                "{%0,%1,%2,%3}, {%4,%5,%6,%7}, {%8,%9}, {%0,%1,%2,%3};"
                : "+f"(acc[nt][0]), "+f"(acc[nt][1]), "+f"(acc[nt][2]), "+f"(acc[nt][3])
                : "r"(a0), "r"(a1), "r"(a2), "r"(a3), "r"(b0), "r"(b1));
        }
    }

    int row0 = row0g + rbase + g;
    int row1 = row0 + 8;
#pragma unroll
    for (int nt = 0; nt < 16; nt++) {
        int col = nt * 8 + 2 * t;
        if (row0 < n)
            *(__half2*)(g_xwh + (size_t)row0 * 128 + col) = __floats2half2_rn(acc[nt][0], acc[nt][1]);
        if (row1 < n)
            *(__half2*)(g_xwh + (size_t)row1 * 128 + col) = __floats2half2_rn(acc[nt][2], acc[nt][3]);
    }

#pragma unroll
    for (int h = 0; h < NH; h++) {
        float dt0 = 0.f, ds0 = 0.f, dt1 = 0.f, ds1 = 0.f;
#pragma unroll
        for (int j = 0; j < 2; j++) {
            int nt = 2 * h + j;
            int cw = j * 8 + 2 * t;
            float at0 = sAtt[h * 32 + cw],      at1 = sAtt[h * 32 + cw + 1];
            float as0 = sAtt[h * 32 + 16 + cw], as1 = sAtt[h * 32 + 16 + cw + 1];
            dt0 += acc[nt][0] * at0 + acc[nt][1] * at1;
            ds0 += acc[nt][0] * as0 + acc[nt][1] * as1;
            dt1 += acc[nt][2] * at0 + acc[nt][3] * at1;
            ds1 += acc[nt][2] * as0 + acc[nt][3] * as1;
        }
        dt0 += __shfl_xor_sync(0xffffffff, dt0, 1); dt0 += __shfl_xor_sync(0xffffffff, dt0, 2);
        ds0 += __shfl_xor_sync(0xffffffff, ds0, 1); ds0 += __shfl_xor_sync(0xffffffff, ds0, 2);
        dt1 += __shfl_xor_sync(0xffffffff, dt1, 1); dt1 += __shfl_xor_sync(0xffffffff, dt1, 2);
        ds1 += __shfl_xor_sync(0xffffffff, ds1, 1); ds1 += __shfl_xor_sync(0xffffffff, ds1, 2);
        if (t == 0) {
            if (row0 < n) { g_atgt[row0 * NH + h] = dt0; g_asrc[row0 * NH + h] = ds0; }
            if (row1 < n) { g_atgt[row1 * NH + h] = dt1; g_asrc[row1 * NH + h] = ds1; }
        }
    }
}

// ---------------------------------------------------------------------------
// CSR build: histogram -> 3-phase exclusive scan -> permute
// ---------------------------------------------------------------------------
__global__ void k_hist(const int* __restrict__ ei32, int E) {
    int i = blockIdx.x * blockDim.x + threadIdx.x;
    if (i >= E) return;
    int d = edge_at(ei32, E + i, g_is64);
    atomicAdd(&g_deg[d], 1);
}

__global__ void k_scan1(int n) {
    int i = blockIdx.x * 256 + threadIdx.x;
    int lane = threadIdx.x & 31, w = threadIdx.x >> 5;
    int v = (i < n) ? g_deg[i] : 0;
    int x = v;
#pragma unroll
    for (int o = 1; o < 32; o <<= 1) {
        int y = __shfl_up_sync(0xffffffff, x, o);
        if (lane >= o) x += y;
    }
    __shared__ int wsum[8];
    if (lane == 31) wsum[w] = x;
    __syncthreads();
    if (threadIdx.x < 8) {
        int s = wsum[threadIdx.x];
#pragma unroll
        for (int o = 1; o < 8; o <<= 1) {
            int y = __shfl_up_sync(0xff, s, o);
            if ((int)threadIdx.x >= o) s += y;
        }
        wsum[threadIdx.x] = s;
    }
    __syncthreads();
    int base = (w > 0) ? wsum[w - 1] : 0;
    if (i < n) g_start[i] = base + x - v;
    if (threadIdx.x == 0) g_bsum[blockIdx.x] = wsum[7];
}

__global__ void k_scan2(int nb) {
    int i = threadIdx.x;
    int lane = i & 31, w = i >> 5;
    int v = (i < nb) ? g_bsum[i] : 0;
    int x = v;
#pragma unroll
    for (int o = 1; o < 32; o <<= 1) {
        int y = __shfl_up_sync(0xffffffff, x, o);
        if (lane >= o) x += y;
    }
    __shared__ int wsum[16];
    if (lane == 31) wsum[w] = x;
    __syncthreads();
    if (i < 16) {
        int s = wsum[i];
#pragma unroll
        for (int o = 1; o < 16; o <<= 1) {
            int y = __shfl_up_sync(0xffff, s, o);
            if (i >= o) s += y;
        }
        wsum[i] = s;
    }
    __syncthreads();
    int base = (w > 0) ? wsum[w - 1] : 0;
    if (i < nb) g_bsum[i] = base + x - v;
}

__global__ void k_scan3(int n) {
    int i = blockIdx.x * 256 + threadIdx.x;
    if (i < n) g_start[i] += g_bsum[blockIdx.x];
}

__global__ void k_permute(const int* __restrict__ ei32, int E) {
    int i = blockIdx.x * blockDim.x + threadIdx.x;
    if (i >= E) return;
    int sh = g_is64;
    int s = edge_at(ei32, i, sh);
    int d = edge_at(ei32, E + i, sh);
    int pos = atomicAdd(&g_start[d], 1);   // g_start becomes end-of-bucket
    g_srcidx[pos] = s;
}

// ---------------------------------------------------------------------------
// K5: gather — one warp per dst node, software-pipelined, fp16 xw (256B/edge).
// Lane L handles channels [4L, 4L+4) => head h = L>>2.
// ---------------------------------------------------------------------------
__global__ void __launch_bounds__(256) k_gather(float* __restrict__ out,
                                                const float* __restrict__ bias, int n) {
    int gw = (blockIdx.x * blockDim.x + threadIdx.x) >> 5;
    if (gw >= n) return;
    int lane = threadIdx.x & 31;
    int d = gw;
    int h = lane >> 2;
    float atgtv = g_atgt[d * NH + h];
    int deg = g_deg[d];
    int start = g_start[d] - deg;          // g_start holds end after permute
    float4 acc = make_float4(0.f, 0.f, 0.f, 0.f);
    float den = 0.f;
    const uint2* xw2 = (const uint2*)g_xwh;   // 4 halves per lane

    if (deg > 0) {
        int s_n = g_srcidx[start];
        float as_n = g_asrc[s_n * NH + h];
        uint2 v_n = __ldg(xw2 + (size_t)s_n * 32 + lane);
        for (int j = 0; j < deg; j++) {
            float as = as_n;
            uint2 vr = v_n;
            if (j + 1 < deg) {
                int s2 = g_srcidx[start + j + 1];
                as_n = g_asrc[s2 * NH + h];
                v_n = __ldg(xw2 + (size_t)s2 * 32 + lane);
            }
            float a = atgtv + as;
            a = a > 0.f ? a : 0.2f * a;
            float ex = __expf(a);
            float2 lo = __half22float2(*(__half2*)&vr.x);
            float2 hi = __half22float2(*(__half2*)&vr.y);
            acc.x += ex * lo.x; acc.y += ex * lo.y;
            acc.z += ex * hi.x; acc.w += ex * hi.y;
            den += ex;
        }
    }
    float inv = (den > 0.f) ? 1.f / den : 0.f;
    float4 b = ((const float4*)bias)[lane];
    float4 o;
    o.x = acc.x * inv + b.x; o.y = acc.y * inv + b.y;
    o.z = acc.z * inv + b.z; o.w = acc.w * inv + b.w;
    ((float4*)out)[(size_t)d * 32 + lane] = o;
}

// ---------------------------------------------------------------------------
extern "C" void kernel_launch(void* const* d_in, const int* in_sizes, int n_in,
                              void* d_out, int out_size) {
    int order[16];
    for (int i = 0; i < n_in; i++) order[i] = i;
    for (int a = 0; a < n_in; a++)
        for (int b = a + 1; b < n_in; b++)
            if (in_sizes[order[b]] > in_sizes[order[a]]) {
                int t = order[a]; order[a] = order[b]; order[b] = t;
            }
    const float* x    = (const float*)d_in[order[0]];
    const int*   ei32 = (const int*)  d_in[order[1]];
    const float* w    = (const float*)d_in[order[3]];
    const float* att  = (const float*)d_in[order[4]];
    const float* bias = (const float*)d_in[order[5]];
    float*       out  = (float*)d_out;

    int n = in_sizes[order[0]] / 128;
    int E = in_sizes[order[1]] / 2;

    static cudaStream_t s2 = nullptr;
    static cudaEvent_t evFork = nullptr, evJoin = nullptr;
    if (!s2) {
        cudaStreamCreateWithFlags(&s2, cudaStreamNonBlocking);
        cudaEventCreateWithFlags(&evFork, cudaEventDisableTiming);
        cudaEventCreateWithFlags(&evJoin, cudaEventDisableTiming);
    }

    int nb = (n + 255) / 256;
    int eb = (E + 255) / 256;

    // fork immediately: main = W-prep + GEMM; s2 = edge prep + CSR build
    cudaEventRecord(evFork, 0);
    cudaStreamWaitEvent(s2, evFork, 0);

    k_prep_w<<<64, 256>>>(w);
    int smem_bytes = (2 * 128 * SA_STRIDE + 256) * sizeof(float);
    cudaFuncSetAttribute(k_gemm_tf32, cudaFuncAttributeMaxDynamicSharedMemorySize, smem_bytes);
    k_gemm_tf32<<<(n + 127) / 128, 256, smem_bytes>>>(x, att, n);

    k_prep_e<<<nb, 256, 0, s2>>>(ei32, n, E);
    k_hist<<<eb, 256, 0, s2>>>(ei32, E);
    k_scan1<<<nb, 256, 0, s2>>>(n);
    k_scan2<<<1, 512, 0, s2>>>(nb);
    k_scan3<<<nb, 256, 0, s2>>>(n);
    k_permute<<<eb, 256, 0, s2>>>(ei32, E);

    cudaEventRecord(evJoin, s2);
    cudaStreamWaitEvent(0, evJoin, 0);

    k_gather<<<(n * 32 + 255) / 256, 256>>>(out, bias, n);
}